// round 1
// baseline (speedup 1.0000x reference)
#include <cuda_runtime.h>
#include <math.h>

#define MTOK 4096
#define HDIM 2048
#define NEXP 8
#define MOEI 1408
#define SHI  5632
#define CAP  4096

// ---------------- static device scratch (no allocations allowed) ----------------
__device__ float g_gu  [(size_t)MTOK * (2 * SHI)];        // shared gate_up out   184 MB
__device__ float g_actS[(size_t)MTOK * SHI];              // shared act            92 MB
__device__ float g_gateS[MTOK];                           // sigmoid token gate
__device__ int   g_counts[NEXP];
__device__ int   g_perm [NEXP * CAP];                     // expert -> token list
__device__ int   g_slot [MTOK * 2];                       // token -> slot in expert buffers
__device__ float g_wt   [MTOK * 2];                       // token -> routing weight
__device__ float g_egu  [(size_t)NEXP * CAP * (2 * MOEI)];// expert gate_up out   369 MB
__device__ float g_eact [(size_t)NEXP * CAP * MOEI];      // expert act           184 MB
__device__ float g_moe  [(size_t)NEXP * CAP * HDIM];      // expert down out      268 MB

__global__ void init_kernel() {
    if (threadIdx.x < NEXP) g_counts[threadIdx.x] = 0;
}

// ---------------- router: logits, softmax, top-2, assignment lists ----------------
__global__ void router_kernel(const float* __restrict__ x,
                              const float* __restrict__ gate_w,
                              const float* __restrict__ shared_gate_w)
{
    int m    = blockIdx.x;
    int tid  = threadIdx.x;
    int w    = tid >> 5;
    int lane = tid & 31;
    const float* xr = x + (size_t)m * HDIM;

    __shared__ float s_log[NEXP];
    __shared__ float s_sg;

    // each warp computes one expert logit
    {
        const float* gw = gate_w + (size_t)w * HDIM;
        float sum = 0.f;
        for (int k = lane; k < HDIM; k += 32) sum += xr[k] * gw[k];
        #pragma unroll
        for (int o = 16; o; o >>= 1) sum += __shfl_xor_sync(0xffffffffu, sum, o);
        if (lane == 0) s_log[w] = sum;
    }
    // warp 0 also computes shared gate logit
    if (w == 0) {
        float sg = 0.f;
        for (int k = lane; k < HDIM; k += 32) sg += xr[k] * shared_gate_w[k];
        #pragma unroll
        for (int o = 16; o; o >>= 1) sg += __shfl_xor_sync(0xffffffffu, sg, o);
        if (lane == 0) s_sg = sg;
    }
    __syncthreads();

    if (tid == 0) {
        float mx = -1e30f;
        #pragma unroll
        for (int e = 0; e < NEXP; e++) mx = fmaxf(mx, s_log[e]);
        float p[NEXP]; float den = 0.f;
        #pragma unroll
        for (int e = 0; e < NEXP; e++) { p[e] = expf(s_log[e] - mx); den += p[e]; }
        float inv = 1.f / den;

        int i1 = 0; float p1 = -1.f;
        #pragma unroll
        for (int e = 0; e < NEXP; e++) if (p[e] > p1) { p1 = p[e]; i1 = e; }
        int i2 = -1; float p2 = -1.f;
        #pragma unroll
        for (int e = 0; e < NEXP; e++) { if (e == i1) continue; if (p[e] > p2) { p2 = p[e]; i2 = e; } }
        p1 *= inv; p2 *= inv;

        g_gateS[m] = 1.f / (1.f + expf(-s_sg));

        int pos1 = atomicAdd(&g_counts[i1], 1);
        g_perm[i1 * CAP + pos1] = m;
        g_slot[2 * m + 0] = i1 * CAP + pos1;
        g_wt  [2 * m + 0] = p1;

        int pos2 = atomicAdd(&g_counts[i2], 1);
        g_perm[i2 * CAP + pos2] = m;
        g_slot[2 * m + 1] = i2 * CAP + pos2;
        g_wt  [2 * m + 1] = p2;
    }
}

// ---------------- generic tiled fp32 GEMM: C = A * B^T ----------------
// A: rows K-contiguous (optionally gathered via perm), B: rows K-contiguous.
// blockIdx.z selects an "expert" segment via strides; counts (optional) bounds rows.
#define BM 128
#define BN 128
#define BK 16

__global__ __launch_bounds__(256, 2)
void sgemm_nt(const float* __restrict__ A, const float* __restrict__ B,
              float* __restrict__ C, int N, int K,
              long strideA, long strideB, long strideC,
              const int* __restrict__ counts, int Mfull,
              const int* __restrict__ perm,
              const float* __restrict__ rowScale)
{
    int e   = blockIdx.z;
    int cnt = counts ? counts[e] : Mfull;
    int m0  = blockIdx.y * BM;
    if (m0 >= cnt) return;
    int n0  = blockIdx.x * BN;

    A += (long)e * strideA;
    B += (long)e * strideB;
    C += (long)e * strideC;
    const int* pm = perm ? (perm + e * CAP) : (const int*)0;

    __shared__ float As[BK][BM + 4];
    __shared__ float Bs[BK][BN + 4];

    int tid = threadIdx.x;
    int tx  = tid & 15;
    int ty  = tid >> 4;

    int aR0 = tid >> 2;         // 0..63
    int aR1 = aR0 + 64;         // 64..127
    int kq  = (tid & 3) << 2;   // 0,4,8,12

    int  gr0 = m0 + aR0, gr1 = m0 + aR1;
    bool v0  = gr0 < cnt, v1 = gr1 < cnt;
    long ar0 = pm ? (long)(v0 ? pm[gr0] : 0) : (long)gr0;
    long ar1 = pm ? (long)(v1 ? pm[gr1] : 0) : (long)gr1;
    const float* Ap0 = A + ar0 * K + kq;
    const float* Ap1 = A + ar1 * K + kq;
    const float* Bp0 = B + (long)(n0 + aR0) * K + kq;
    const float* Bp1 = B + (long)(n0 + aR1) * K + kq;

    float acc[8][8];
    #pragma unroll
    for (int i = 0; i < 8; i++)
        #pragma unroll
        for (int j = 0; j < 8; j++) acc[i][j] = 0.f;

    for (int k0 = 0; k0 < K; k0 += BK) {
        float4 a0 = v0 ? *(const float4*)(Ap0 + k0) : make_float4(0.f, 0.f, 0.f, 0.f);
        float4 a1 = v1 ? *(const float4*)(Ap1 + k0) : make_float4(0.f, 0.f, 0.f, 0.f);
        float4 b0 = *(const float4*)(Bp0 + k0);
        float4 b1 = *(const float4*)(Bp1 + k0);

        As[kq + 0][aR0] = a0.x; As[kq + 1][aR0] = a0.y; As[kq + 2][aR0] = a0.z; As[kq + 3][aR0] = a0.w;
        As[kq + 0][aR1] = a1.x; As[kq + 1][aR1] = a1.y; As[kq + 2][aR1] = a1.z; As[kq + 3][aR1] = a1.w;
        Bs[kq + 0][aR0] = b0.x; Bs[kq + 1][aR0] = b0.y; Bs[kq + 2][aR0] = b0.z; Bs[kq + 3][aR0] = b0.w;
        Bs[kq + 0][aR1] = b1.x; Bs[kq + 1][aR1] = b1.y; Bs[kq + 2][aR1] = b1.z; Bs[kq + 3][aR1] = b1.w;
        __syncthreads();

        #pragma unroll
        for (int kk = 0; kk < BK; kk++) {
            float a[8], b[8];
            #pragma unroll
            for (int i = 0; i < 8; i++) a[i] = As[kk][ty * 8 + i];
            #pragma unroll
            for (int j = 0; j < 8; j++) b[j] = Bs[kk][tx * 8 + j];
            #pragma unroll
            for (int i = 0; i < 8; i++)
                #pragma unroll
                for (int j = 0; j < 8; j++)
                    acc[i][j] = fmaf(a[i], b[j], acc[i][j]);
        }
        __syncthreads();
    }

    #pragma unroll
    for (int i = 0; i < 8; i++) {
        int row = m0 + ty * 8 + i;
        if (row >= cnt) continue;
        float s = rowScale ? rowScale[row] : 1.f;
        float* Crow = C + (long)row * N + n0 + tx * 8;
        float4 o0, o1;
        o0.x = acc[i][0] * s; o0.y = acc[i][1] * s; o0.z = acc[i][2] * s; o0.w = acc[i][3] * s;
        o1.x = acc[i][4] * s; o1.y = acc[i][5] * s; o1.z = acc[i][6] * s; o1.w = acc[i][7] * s;
        *(float4*)(Crow)     = o0;
        *(float4*)(Crow + 4) = o1;
    }
}

// ---------------- SiLU(gate) * up ----------------
// gu rows are [2*I]; act rows are [I]. grid.y = row, grid.x covers I/4.
__global__ void silu_mul_kernel(const float* __restrict__ gu, float* __restrict__ act,
                                int I, const int* __restrict__ counts)
{
    int row = blockIdx.y;
    int c4  = blockIdx.x * blockDim.x + threadIdx.x;
    int I4  = I >> 2;
    if (c4 >= I4) return;
    if (counts) {
        int e = row / CAP, lr = row % CAP;
        if (lr >= counts[e]) return;
    }
    size_t base = (size_t)row * (2 * I);
    int ci = c4 << 2;
    float4 g4 = *(const float4*)(gu + base + ci);
    float4 u4 = *(const float4*)(gu + base + I + ci);
    float4 o;
    o.x = g4.x / (1.f + expf(-g4.x)) * u4.x;
    o.y = g4.y / (1.f + expf(-g4.y)) * u4.y;
    o.z = g4.z / (1.f + expf(-g4.z)) * u4.z;
    o.w = g4.w / (1.f + expf(-g4.w)) * u4.w;
    *(float4*)(act + (size_t)row * I + ci) = o;
}

// ---------------- combine: out += w0*h(e0) + w1*h(e1) ----------------
__global__ void combine_kernel(float* __restrict__ out)
{
    int m  = blockIdx.y;
    int c4 = blockIdx.x * blockDim.x + threadIdx.x;
    if (c4 >= (HDIM >> 2)) return;
    int ci = c4 << 2;
    int   s0 = g_slot[2 * m + 0], s1 = g_slot[2 * m + 1];
    float w0 = g_wt  [2 * m + 0], w1 = g_wt  [2 * m + 1];
    float4 h0 = *(const float4*)(g_moe + (size_t)s0 * HDIM + ci);
    float4 h1 = *(const float4*)(g_moe + (size_t)s1 * HDIM + ci);
    float4 o  = *(float4*)(out + (size_t)m * HDIM + ci);
    o.x += w0 * h0.x + w1 * h1.x;
    o.y += w0 * h0.y + w1 * h1.y;
    o.z += w0 * h0.z + w1 * h1.z;
    o.w += w0 * h0.w + w1 * h1.w;
    *(float4*)(out + (size_t)m * HDIM + ci) = o;
}

// ---------------- launch ----------------
extern "C" void kernel_launch(void* const* d_in, const int* in_sizes, int n_in,
                              void* d_out, int out_size)
{
    (void)in_sizes; (void)n_in; (void)out_size;
    const float* x    = (const float*)d_in[0];
    const float* gw   = (const float*)d_in[1];
    const float* sgw  = (const float*)d_in[2];
    const float* sguw = (const float*)d_in[3];
    const float* sdw  = (const float*)d_in[4];
    const float* w13  = (const float*)d_in[5];
    const float* w2   = (const float*)d_in[6];
    float* out = (float*)d_out;

    float *gu, *actS, *gateS, *egu, *eact, *moe;
    int *counts, *perm;
    cudaGetSymbolAddress((void**)&gu,    g_gu);
    cudaGetSymbolAddress((void**)&actS,  g_actS);
    cudaGetSymbolAddress((void**)&gateS, g_gateS);
    cudaGetSymbolAddress((void**)&egu,   g_egu);
    cudaGetSymbolAddress((void**)&eact,  g_eact);
    cudaGetSymbolAddress((void**)&moe,   g_moe);
    cudaGetSymbolAddress((void**)&counts, g_counts);
    cudaGetSymbolAddress((void**)&perm,   g_perm);

    init_kernel<<<1, 32>>>();
    router_kernel<<<MTOK, 256>>>(x, gw, sgw);

    // shared expert: gate_up GEMM -> silu*mul -> down GEMM (with sigmoid gate epilogue)
    sgemm_nt<<<dim3((2 * SHI) / BN, MTOK / BM, 1), 256>>>(
        x, sguw, gu, 2 * SHI, HDIM, 0, 0, 0, nullptr, MTOK, nullptr, nullptr);
    silu_mul_kernel<<<dim3((SHI / 4 + 255) / 256, MTOK, 1), 256>>>(gu, actS, SHI, nullptr);
    sgemm_nt<<<dim3(HDIM / BN, MTOK / BM, 1), 256>>>(
        actS, sdw, out, HDIM, SHI, 0, 0, 0, nullptr, MTOK, nullptr, gateS);

    // routed experts: gathered gate_up GEMM -> silu*mul -> down GEMM
    sgemm_nt<<<dim3((2 * MOEI) / BN, CAP / BM, NEXP), 256>>>(
        x, w13, egu, 2 * MOEI, HDIM,
        0, (long)(2 * MOEI) * HDIM, (long)CAP * (2 * MOEI),
        counts, CAP, perm, nullptr);
    silu_mul_kernel<<<dim3((MOEI / 4 + 255) / 256, NEXP * CAP, 1), 256>>>(egu, eact, MOEI, counts);
    sgemm_nt<<<dim3(HDIM / BN, CAP / BM, NEXP), 256>>>(
        eact, w2, moe, HDIM, MOEI,
        (long)CAP * MOEI, (long)HDIM * MOEI, (long)CAP * HDIM,
        counts, CAP, nullptr, nullptr);

    // out = shared + sum_k w_k * expert_k
    combine_kernel<<<dim3((HDIM / 4 + 255) / 256, MTOK, 1), 256>>>(out);
}

// round 6
// speedup vs baseline: 2.1035x; 2.1035x over previous
#include <cuda_runtime.h>
#include <cstdint>
#include <math.h>

#define MTOK 4096
#define HDIM 2048
#define NEXP 8
#define MOEI 1408
#define SHI  5632
#define CAP  4096

#define BM 128
#define BN 128
#define BK 32
#define NSTAGE 4
#define ASTR 36                                  // smem row stride in floats
#define STAGE_FLOATS (2 * 128 * ASTR)            // A tile then B tile
#define STAGE_BYTES  (STAGE_FLOATS * 4)          // 36864
#define SMEM_TOTAL   (NSTAGE * STAGE_BYTES)      // 147456

// ---------------- static device scratch ----------------
__device__ float g_actS[(size_t)MTOK * SHI];
__device__ float g_eact[(size_t)NEXP * CAP * MOEI];
__device__ float g_moe [(size_t)NEXP * CAP * HDIM];
__device__ float g_gateS[MTOK];
__device__ int   g_counts[NEXP];
__device__ int   g_perm [NEXP * CAP];
__device__ int   g_slot [MTOK * 2];
__device__ float g_wt   [MTOK * 2];

// ---------------- PTX helpers ----------------
__device__ __forceinline__ uint32_t smem_u32(const void* p) {
    uint32_t a;
    asm("{ .reg .u64 t; cvta.to.shared.u64 t, %1; cvt.u32.u64 %0, t; }" : "=r"(a) : "l"(p));
    return a;
}
#define CP16(dst, src) \
    asm volatile("cp.async.cg.shared.global [%0], [%1], 16;" :: "r"(dst), "l"(src))
#define CP_COMMIT() asm volatile("cp.async.commit_group;" ::: "memory")
#define CP_WAIT(n)  asm volatile("cp.async.wait_group %0;" :: "n"(n) : "memory")

__device__ __forceinline__ uint32_t to_tf32(float f) {
    uint32_t r;
    asm("cvt.rna.tf32.f32 %0, %1;" : "=r"(r) : "f"(f));
    return r;
}
__device__ __forceinline__ void mma_tf32(float* c, const uint32_t* a, const uint32_t* b) {
    asm volatile(
        "mma.sync.aligned.m16n8k8.row.col.f32.tf32.tf32.f32 "
        "{%0,%1,%2,%3}, {%4,%5,%6,%7}, {%8,%9}, {%0,%1,%2,%3};"
        : "+f"(c[0]), "+f"(c[1]), "+f"(c[2]), "+f"(c[3])
        : "r"(a[0]), "r"(a[1]), "r"(a[2]), "r"(a[3]), "r"(b[0]), "r"(b[1]));
}

// ---------------- small kernels ----------------
__global__ void init_kernel() {
    if (threadIdx.x < NEXP) g_counts[threadIdx.x] = 0;
}

__global__ void router_kernel(const float* __restrict__ x,
                              const float* __restrict__ gate_w,
                              const float* __restrict__ shared_gate_w)
{
    int m = blockIdx.x, tid = threadIdx.x, w = tid >> 5, lane = tid & 31;
    const float* xr = x + (size_t)m * HDIM;
    __shared__ float s_log[NEXP];
    __shared__ float s_sg;
    {
        const float* gw = gate_w + (size_t)w * HDIM;
        float sum = 0.f;
        for (int k = lane; k < HDIM; k += 32) sum += xr[k] * gw[k];
        #pragma unroll
        for (int o = 16; o; o >>= 1) sum += __shfl_xor_sync(0xffffffffu, sum, o);
        if (lane == 0) s_log[w] = sum;
    }
    if (w == 0) {
        float sg = 0.f;
        for (int k = lane; k < HDIM; k += 32) sg += xr[k] * shared_gate_w[k];
        #pragma unroll
        for (int o = 16; o; o >>= 1) sg += __shfl_xor_sync(0xffffffffu, sg, o);
        if (lane == 0) s_sg = sg;
    }
    __syncthreads();
    if (tid == 0) {
        float mx = -1e30f;
        #pragma unroll
        for (int e = 0; e < NEXP; e++) mx = fmaxf(mx, s_log[e]);
        float p[NEXP]; float den = 0.f;
        #pragma unroll
        for (int e = 0; e < NEXP; e++) { p[e] = expf(s_log[e] - mx); den += p[e]; }
        float inv = 1.f / den;
        int i1 = 0; float p1 = -1.f;
        #pragma unroll
        for (int e = 0; e < NEXP; e++) if (p[e] > p1) { p1 = p[e]; i1 = e; }
        int i2 = -1; float p2 = -1.f;
        #pragma unroll
        for (int e = 0; e < NEXP; e++) { if (e == i1) continue; if (p[e] > p2) { p2 = p[e]; i2 = e; } }
        p1 *= inv; p2 *= inv;
        g_gateS[m] = 1.f / (1.f + expf(-s_sg));
        int pos1 = atomicAdd(&g_counts[i1], 1);
        g_perm[i1 * CAP + pos1] = m;
        g_slot[2 * m + 0] = i1 * CAP + pos1;
        g_wt  [2 * m + 0] = p1;
        int pos2 = atomicAdd(&g_counts[i2], 1);
        g_perm[i2 * CAP + pos2] = m;
        g_slot[2 * m + 1] = i2 * CAP + pos2;
        g_wt  [2 * m + 1] = p2;
    }
}

__global__ void combine_kernel(float* __restrict__ out)
{
    int m  = blockIdx.y;
    int c4 = blockIdx.x * blockDim.x + threadIdx.x;
    if (c4 >= (HDIM >> 2)) return;
    int ci = c4 << 2;
    int   s0 = g_slot[2 * m + 0], s1 = g_slot[2 * m + 1];
    float w0 = g_wt  [2 * m + 0], w1 = g_wt  [2 * m + 1];
    float4 h0 = *(const float4*)(g_moe + (size_t)s0 * HDIM + ci);
    float4 h1 = *(const float4*)(g_moe + (size_t)s1 * HDIM + ci);
    float4 o  = *(float4*)(out + (size_t)m * HDIM + ci);
    o.x += w0 * h0.x + w1 * h1.x;
    o.y += w0 * h0.y + w1 * h1.y;
    o.z += w0 * h0.z + w1 * h1.z;
    o.w += w0 * h0.w + w1 * h1.w;
    *(float4*)(out + (size_t)m * HDIM + ci) = o;
}

// ---------------- tf32 mma.sync GEMM ----------------
// MODE 0: act[row][n0g+c] = silu(A·Wg^T) * (A·Wu^T); B rows: nl<64 -> gate row n0g+nl,
//         nl>=64 -> up row I+n0g+(nl-64); output tile 128x64.
// MODE 1: C = (A·W^T) * rowScale; output tile 128x128.
template<int MODE>
__global__ __launch_bounds__(256, 1)
void mma_gemm(const float* __restrict__ Abase, const float* __restrict__ Wbase,
              float* __restrict__ Cbase, int I, int K,
              long sA, long sW, long sC,
              const int* __restrict__ counts, int Mfull,
              const int* __restrict__ perm, const float* __restrict__ rowScale)
{
    int e = blockIdx.z;
    int cnt = counts ? counts[e] : Mfull;
    int m0 = blockIdx.y * BM;
    if (m0 >= cnt) return;

    const float* A = Abase + (long)e * sA;
    const float* W = Wbase + (long)e * sW;
    float* C = Cbase + (long)e * sC;
    const int* pm = perm ? perm + e * CAP : (const int*)0;

    extern __shared__ float smem[];
    uint32_t smem_b = smem_u32(smem);

    int tid = threadIdx.x;
    int lane = tid & 31, wid = tid >> 5;
    int warpM = wid & 3, warpN = wid >> 2;

    // ---- producer mapping: thread t fills row lr, k-half kh ----
    int lr = tid >> 1;
    int kh = (tid & 1) * 16;
    int gr = m0 + lr;
    long arow = pm ? (long)((gr < cnt) ? pm[gr] : 0) : (long)((gr < cnt) ? gr : 0);
    const float* aptr = A + arow * (long)K + kh;
    long wrow;
    int n0g = 0;
    if (MODE == 0) {
        n0g = blockIdx.x * 64;
        wrow = (lr < 64) ? (long)(n0g + lr) : (long)(I + n0g + (lr - 64));
    } else {
        wrow = (long)(blockIdx.x * BN + lr);
    }
    const float* bptr = W + wrow * (long)K + kh;
    uint32_t adst = smem_b + (uint32_t)lr * (ASTR * 4) + (uint32_t)kh * 4;
    uint32_t bdst = adst + 128 * ASTR * 4;

    int KI = K / BK;

    // prologue: stages 0..NSTAGE-2
    #pragma unroll
    for (int s = 0; s < NSTAGE - 1; s++) {
        const float* a = aptr + s * BK;
        const float* b = bptr + s * BK;
        uint32_t so = (uint32_t)s * STAGE_BYTES;
        #pragma unroll
        for (int j = 0; j < 4; j++) CP16(adst + so + j * 16, a + j * 4);
        #pragma unroll
        for (int j = 0; j < 4; j++) CP16(bdst + so + j * 16, b + j * 4);
        CP_COMMIT();
    }

    float acc[2][8][4];
    #pragma unroll
    for (int i = 0; i < 2; i++)
        #pragma unroll
        for (int j = 0; j < 8; j++)
            #pragma unroll
            for (int q = 0; q < 4; q++) acc[i][j][q] = 0.f;

    int r = lane >> 2, cq = lane & 3;

    #pragma unroll 1
    for (int k = 0; k < KI; k++) {
        CP_WAIT(NSTAGE - 2);
        __syncthreads();

        // issue next stage immediately (overwrites stage used at iter k-1; safe after sync)
        int kn = k + NSTAGE - 1;
        if (kn < KI) {
            const float* a = aptr + kn * BK;
            const float* b = bptr + kn * BK;
            uint32_t so = (uint32_t)(kn % NSTAGE) * STAGE_BYTES;
            #pragma unroll
            for (int j = 0; j < 4; j++) CP16(adst + so + j * 16, a + j * 4);
            #pragma unroll
            for (int j = 0; j < 4; j++) CP16(bdst + so + j * 16, b + j * 4);
            CP_COMMIT();
        }

        const float* As = smem + (k % NSTAGE) * STAGE_FLOATS;
        const float* Bs = As + 128 * ASTR;

        #pragma unroll
        for (int kc = 0; kc < BK; kc += 8) {
            uint32_t af[2][4], bf[8][2];
            #pragma unroll
            for (int mt = 0; mt < 2; mt++) {
                int mb = warpM * 32 + mt * 16;
                af[mt][0] = to_tf32(As[(mb + r)     * ASTR + kc + cq]);
                af[mt][1] = to_tf32(As[(mb + 8 + r) * ASTR + kc + cq]);
                af[mt][2] = to_tf32(As[(mb + r)     * ASTR + kc + 4 + cq]);
                af[mt][3] = to_tf32(As[(mb + 8 + r) * ASTR + kc + 4 + cq]);
            }
            #pragma unroll
            for (int nt = 0; nt < 8; nt++) {
                int nb = warpN * 64 + nt * 8;
                bf[nt][0] = to_tf32(Bs[(nb + r) * ASTR + kc + cq]);
                bf[nt][1] = to_tf32(Bs[(nb + r) * ASTR + kc + 4 + cq]);
            }
            #pragma unroll
            for (int mt = 0; mt < 2; mt++)
                #pragma unroll
                for (int nt = 0; nt < 8; nt++)
                    mma_tf32(acc[mt][nt], af[mt], bf[nt]);
        }
    }

    if (MODE == 1) {
        int n0 = blockIdx.x * BN;
        int c2 = (lane & 3) * 2;
        #pragma unroll
        for (int mt = 0; mt < 2; mt++) {
            #pragma unroll
            for (int half = 0; half < 2; half++) {
                int row = m0 + warpM * 32 + mt * 16 + half * 8 + r;
                if (row >= cnt) continue;
                float sc = rowScale ? rowScale[row] : 1.f;
                float* crow = C + (long)row * I + n0 + warpN * 64;
                #pragma unroll
                for (int nt = 0; nt < 8; nt++) {
                    float2 v;
                    v.x = acc[mt][nt][half * 2 + 0] * sc;
                    v.y = acc[mt][nt][half * 2 + 1] * sc;
                    *(float2*)(crow + nt * 8 + c2) = v;
                }
            }
        }
    } else {
        // stage accumulators through smem to pair gate/up columns
        __syncthreads();                // all cp.async groups drained by final waits
        float* Cs = smem;               // [128][132]
        int c2 = (lane & 3) * 2;
        #pragma unroll
        for (int mt = 0; mt < 2; mt++)
            #pragma unroll
            for (int half = 0; half < 2; half++) {
                int rr = warpM * 32 + mt * 16 + half * 8 + r;
                #pragma unroll
                for (int nt = 0; nt < 8; nt++) {
                    float2 v;
                    v.x = acc[mt][nt][half * 2 + 0];
                    v.y = acc[mt][nt][half * 2 + 1];
                    *(float2*)(Cs + rr * 132 + warpN * 64 + nt * 8 + c2) = v;
                }
            }
        __syncthreads();
        int row = tid >> 1;
        int cb = (tid & 1) * 32;
        if (m0 + row < cnt) {
            float* crow = C + (long)(m0 + row) * I + n0g;
            #pragma unroll
            for (int j = 0; j < 32; j += 4) {
                float4 g = *(const float4*)(Cs + row * 132 + cb + j);
                float4 u = *(const float4*)(Cs + row * 132 + 64 + cb + j);
                float4 o;
                o.x = g.x / (1.f + __expf(-g.x)) * u.x;
                o.y = g.y / (1.f + __expf(-g.y)) * u.y;
                o.z = g.z / (1.f + __expf(-g.z)) * u.z;
                o.w = g.w / (1.f + __expf(-g.w)) * u.w;
                *(float4*)(crow + cb + j) = o;
            }
        }
    }
}

// ---------------- launch ----------------
extern "C" void kernel_launch(void* const* d_in, const int* in_sizes, int n_in,
                              void* d_out, int out_size)
{
    (void)in_sizes; (void)n_in; (void)out_size;
    const float* x    = (const float*)d_in[0];
    const float* gw   = (const float*)d_in[1];
    const float* sgw  = (const float*)d_in[2];
    const float* sguw = (const float*)d_in[3];
    const float* sdw  = (const float*)d_in[4];
    const float* w13  = (const float*)d_in[5];
    const float* w2   = (const float*)d_in[6];
    float* out = (float*)d_out;

    float *actS, *eact, *moe, *gateS;
    int *counts, *perm;
    cudaGetSymbolAddress((void**)&actS,   g_actS);
    cudaGetSymbolAddress((void**)&eact,   g_eact);
    cudaGetSymbolAddress((void**)&moe,    g_moe);
    cudaGetSymbolAddress((void**)&gateS,  g_gateS);
    cudaGetSymbolAddress((void**)&counts, g_counts);
    cudaGetSymbolAddress((void**)&perm,   g_perm);

    cudaFuncSetAttribute(mma_gemm<0>, cudaFuncAttributeMaxDynamicSharedMemorySize, SMEM_TOTAL);
    cudaFuncSetAttribute(mma_gemm<1>, cudaFuncAttributeMaxDynamicSharedMemorySize, SMEM_TOTAL);

    init_kernel<<<1, 32>>>();
    router_kernel<<<MTOK, 256>>>(x, gw, sgw);

    // shared expert gate_up (fused silu*mul)
    mma_gemm<0><<<dim3(SHI / 64, MTOK / BM, 1), 256, SMEM_TOTAL>>>(
        x, sguw, actS, SHI, HDIM, 0, 0, 0, nullptr, MTOK, nullptr, nullptr);
    // routed experts gate_up (gathered, fused silu*mul)
    mma_gemm<0><<<dim3(MOEI / 64, CAP / BM, NEXP), 256, SMEM_TOTAL>>>(
        x, w13, eact, MOEI, HDIM,
        0, (long)(2 * MOEI) * HDIM, (long)CAP * MOEI,
        counts, CAP, perm, nullptr);
    // shared down (fused sigmoid token gate) -> out
    mma_gemm<1><<<dim3(HDIM / BN, MTOK / BM, 1), 256, SMEM_TOTAL>>>(
        actS, sdw, out, HDIM, SHI, 0, 0, 0, nullptr, MTOK, nullptr, gateS);
    // expert down
    mma_gemm<1><<<dim3(HDIM / BN, CAP / BM, NEXP), 256, SMEM_TOTAL>>>(
        eact, w2, moe, HDIM, MOEI,
        (long)CAP * MOEI, (long)HDIM * MOEI, (long)CAP * HDIM,
        counts, CAP, nullptr, nullptr);

    combine_kernel<<<dim3((HDIM / 4 + 255) / 256, MTOK, 1), 256>>>(out);
}

// round 7
// speedup vs baseline: 2.9181x; 1.3873x over previous
#include <cuda_runtime.h>
#include <cstdint>
#include <math.h>

#define MTOK 4096
#define HDIM 2048
#define NEXP 8
#define MOEI 1408
#define SHI  5632
#define CAP  4096

#define BM 128
#define BN 128
#define BK 32
#define NSTAGE 3
#define STAGE_FLOATS (2 * 128 * 32)              // A tile + B tile, no padding (swizzled)
#define STAGE_BYTES  (STAGE_FLOATS * 4)          // 32768
#define SMEM_TOTAL   (NSTAGE * STAGE_BYTES)      // 98304 -> 2 CTAs/SM

// ---------------- static device scratch ----------------
__device__ float g_xr  [(size_t)MTOK * HDIM];            // tf32-rounded x
__device__ float g_sguwr[(size_t)(2 * SHI) * HDIM];      // rounded shared gate_up w
__device__ float g_sdwr[(size_t)HDIM * SHI];             // rounded shared down w
__device__ float g_w13r[(size_t)NEXP * (2 * MOEI) * HDIM];
__device__ float g_w2r [(size_t)NEXP * HDIM * MOEI];
__device__ float g_actS[(size_t)MTOK * SHI];
__device__ float g_eact[(size_t)NEXP * CAP * MOEI];
__device__ float g_moe [(size_t)NEXP * CAP * HDIM];
__device__ float g_gateS[MTOK];
__device__ int   g_counts[NEXP];
__device__ int   g_perm [NEXP * CAP];
__device__ int   g_slot [MTOK * 2];
__device__ float g_wt   [MTOK * 2];

// ---------------- PTX helpers ----------------
__device__ __forceinline__ uint32_t smem_u32(const void* p) {
    uint32_t a;
    asm("{ .reg .u64 t; cvta.to.shared.u64 t, %1; cvt.u32.u64 %0, t; }" : "=r"(a) : "l"(p));
    return a;
}
#define CP16(dst, src) \
    asm volatile("cp.async.cg.shared.global [%0], [%1], 16;" :: "r"(dst), "l"(src))
#define CP_COMMIT() asm volatile("cp.async.commit_group;" ::: "memory")
#define CP_WAIT(n)  asm volatile("cp.async.wait_group %0;" :: "n"(n) : "memory")

__device__ __forceinline__ uint32_t to_tf32(float f) {
    uint32_t r;
    asm("cvt.rna.tf32.f32 %0, %1;" : "=r"(r) : "f"(f));
    return r;
}
__device__ __forceinline__ void mma_tf32(float* c, const uint32_t* a, const uint32_t* b) {
    asm volatile(
        "mma.sync.aligned.m16n8k8.row.col.f32.tf32.tf32.f32 "
        "{%0,%1,%2,%3}, {%4,%5,%6,%7}, {%8,%9}, {%0,%1,%2,%3};"
        : "+f"(c[0]), "+f"(c[1]), "+f"(c[2]), "+f"(c[3])
        : "r"(a[0]), "r"(a[1]), "r"(a[2]), "r"(a[3]), "r"(b[0]), "r"(b[1]));
}

// ---------------- elementwise tf32 pre-round ----------------
__global__ void round_kernel(const float* __restrict__ in, float* __restrict__ out, long n4)
{
    long i = (long)blockIdx.x * blockDim.x + threadIdx.x;
    if (i >= n4) return;
    float4 v = ((const float4*)in)[i];
    uint4 r;
    r.x = to_tf32(v.x); r.y = to_tf32(v.y); r.z = to_tf32(v.z); r.w = to_tf32(v.w);
    ((uint4*)out)[i] = r;
}

// ---------------- small kernels ----------------
__global__ void init_kernel() {
    if (threadIdx.x < NEXP) g_counts[threadIdx.x] = 0;
}

__global__ void router_kernel(const float* __restrict__ x,
                              const float* __restrict__ gate_w,
                              const float* __restrict__ shared_gate_w)
{
    int m = blockIdx.x, tid = threadIdx.x, w = tid >> 5, lane = tid & 31;
    const float* xr = x + (size_t)m * HDIM;
    __shared__ float s_log[NEXP];
    __shared__ float s_sg;
    {
        const float* gw = gate_w + (size_t)w * HDIM;
        float sum = 0.f;
        for (int k = lane; k < HDIM; k += 32) sum += xr[k] * gw[k];
        #pragma unroll
        for (int o = 16; o; o >>= 1) sum += __shfl_xor_sync(0xffffffffu, sum, o);
        if (lane == 0) s_log[w] = sum;
    }
    if (w == 0) {
        float sg = 0.f;
        for (int k = lane; k < HDIM; k += 32) sg += xr[k] * shared_gate_w[k];
        #pragma unroll
        for (int o = 16; o; o >>= 1) sg += __shfl_xor_sync(0xffffffffu, sg, o);
        if (lane == 0) s_sg = sg;
    }
    __syncthreads();
    if (tid == 0) {
        float mx = -1e30f;
        #pragma unroll
        for (int e = 0; e < NEXP; e++) mx = fmaxf(mx, s_log[e]);
        float p[NEXP]; float den = 0.f;
        #pragma unroll
        for (int e = 0; e < NEXP; e++) { p[e] = expf(s_log[e] - mx); den += p[e]; }
        float inv = 1.f / den;
        int i1 = 0; float p1 = -1.f;
        #pragma unroll
        for (int e = 0; e < NEXP; e++) if (p[e] > p1) { p1 = p[e]; i1 = e; }
        int i2 = -1; float p2 = -1.f;
        #pragma unroll
        for (int e = 0; e < NEXP; e++) { if (e == i1) continue; if (p[e] > p2) { p2 = p[e]; i2 = e; } }
        p1 *= inv; p2 *= inv;
        g_gateS[m] = 1.f / (1.f + expf(-s_sg));
        int pos1 = atomicAdd(&g_counts[i1], 1);
        g_perm[i1 * CAP + pos1] = m;
        g_slot[2 * m + 0] = i1 * CAP + pos1;
        g_wt  [2 * m + 0] = p1;
        int pos2 = atomicAdd(&g_counts[i2], 1);
        g_perm[i2 * CAP + pos2] = m;
        g_slot[2 * m + 1] = i2 * CAP + pos2;
        g_wt  [2 * m + 1] = p2;
    }
}

__global__ void combine_kernel(float* __restrict__ out)
{
    int m  = blockIdx.y;
    int c4 = blockIdx.x * blockDim.x + threadIdx.x;
    if (c4 >= (HDIM >> 2)) return;
    int ci = c4 << 2;
    int   s0 = g_slot[2 * m + 0], s1 = g_slot[2 * m + 1];
    float w0 = g_wt  [2 * m + 0], w1 = g_wt  [2 * m + 1];
    float4 h0 = *(const float4*)(g_moe + (size_t)s0 * HDIM + ci);
    float4 h1 = *(const float4*)(g_moe + (size_t)s1 * HDIM + ci);
    float4 o  = *(float4*)(out + (size_t)m * HDIM + ci);
    o.x += w0 * h0.x + w1 * h1.x;
    o.y += w0 * h0.y + w1 * h1.y;
    o.z += w0 * h0.z + w1 * h1.z;
    o.w += w0 * h0.w + w1 * h1.w;
    *(float4*)(out + (size_t)m * HDIM + ci) = o;
}

// ---------------- tf32 mma.sync GEMM (pre-rounded operands) ----------------
// MODE 0: act = silu(A·Wg^T) * (A·Wu^T), output tile 128x64, rounded to tf32 on store.
// MODE 1: C = (A·W^T) * rowScale, output tile 128x128.
template<int MODE>
__global__ __launch_bounds__(256, 2)
void mma_gemm(const float* __restrict__ Abase, const float* __restrict__ Wbase,
              float* __restrict__ Cbase, int I, int K,
              long sA, long sW, long sC,
              const int* __restrict__ counts, int Mfull,
              const int* __restrict__ perm, const float* __restrict__ rowScale)
{
    int e = blockIdx.z;
    int cnt = counts ? counts[e] : Mfull;
    int m0 = blockIdx.y * BM;
    if (m0 >= cnt) return;

    const float* A = Abase + (long)e * sA;
    const float* W = Wbase + (long)e * sW;
    float* C = Cbase + (long)e * sC;
    const int* pm = perm ? perm + e * CAP : (const int*)0;

    extern __shared__ float smem[];
    uint32_t smem_b = smem_u32(smem);

    int tid = threadIdx.x;
    int lane = tid & 31, wid = tid >> 5;
    int warpM = wid & 3, warpN = wid >> 2;

    // ---- producer mapping: thread t fills row lr, k-half kh (16 floats via 4x CP16) ----
    int lr = tid >> 1;
    int kh = (tid & 1) * 16;
    int gr = m0 + lr;
    long arow = pm ? (long)((gr < cnt) ? pm[gr] : 0) : (long)((gr < cnt) ? gr : 0);
    const float* aptr = A + arow * (long)K + kh;
    long wrow;
    int n0g = 0;
    if (MODE == 0) {
        n0g = blockIdx.x * 64;
        wrow = (lr < 64) ? (long)(n0g + lr) : (long)(I + n0g + (lr - 64));
    } else {
        wrow = (long)(blockIdx.x * BN + lr);
    }
    const float* bptr = W + wrow * (long)K + kh;
    uint32_t xb = (uint32_t)(lr & 7) << 4;                 // swizzle (bytes)
    uint32_t arow_b = smem_b + (uint32_t)lr * 128u;
    uint32_t brow_b = arow_b + 128u * 128u;
    uint32_t kb = (uint32_t)kh * 4u;

    int KI = K / BK;

    // prologue: stages 0..NSTAGE-2
    #pragma unroll
    for (int s = 0; s < NSTAGE - 1; s++) {
        const float* a = aptr + s * BK;
        const float* b = bptr + s * BK;
        uint32_t so = (uint32_t)s * STAGE_BYTES;
        #pragma unroll
        for (int j = 0; j < 4; j++) CP16(arow_b + so + ((kb + j * 16) ^ xb), a + j * 4);
        #pragma unroll
        for (int j = 0; j < 4; j++) CP16(brow_b + so + ((kb + j * 16) ^ xb), b + j * 4);
        CP_COMMIT();
    }

    float acc[2][8][4];
    #pragma unroll
    for (int i = 0; i < 2; i++)
        #pragma unroll
        for (int j = 0; j < 8; j++)
            #pragma unroll
            for (int q = 0; q < 4; q++) acc[i][j][q] = 0.f;

    int r = lane >> 2, cq = lane & 3;
    int xw = r << 2;                                       // swizzle (floats) for reads

    #pragma unroll 1
    for (int k = 0; k < KI; k++) {
        if (k <= KI - NSTAGE) { CP_WAIT(NSTAGE - 2); } else { CP_WAIT(0); }
        __syncthreads();

        int kn = k + NSTAGE - 1;
        if (kn < KI) {
            const float* a = aptr + kn * BK;
            const float* b = bptr + kn * BK;
            uint32_t so = (uint32_t)(kn % NSTAGE) * STAGE_BYTES;
            #pragma unroll
            for (int j = 0; j < 4; j++) CP16(arow_b + so + ((kb + j * 16) ^ xb), a + j * 4);
            #pragma unroll
            for (int j = 0; j < 4; j++) CP16(brow_b + so + ((kb + j * 16) ^ xb), b + j * 4);
            CP_COMMIT();
        }

        const uint32_t* As = (const uint32_t*)(smem + (k % NSTAGE) * STAGE_FLOATS);
        const uint32_t* Bs = As + 128 * 32;

        #pragma unroll
        for (int kc = 0; kc < BK; kc += 8) {
            int cl = (kc + cq) ^ xw;
            int ch = (kc + 4 + cq) ^ xw;
            uint32_t af[2][4], bf[8][2];
            #pragma unroll
            for (int mt = 0; mt < 2; mt++) {
                int mb = warpM * 32 + mt * 16;
                af[mt][0] = As[(mb + r)     * 32 + cl];
                af[mt][1] = As[(mb + 8 + r) * 32 + cl];
                af[mt][2] = As[(mb + r)     * 32 + ch];
                af[mt][3] = As[(mb + 8 + r) * 32 + ch];
            }
            #pragma unroll
            for (int nt = 0; nt < 8; nt++) {
                int nb = warpN * 64 + nt * 8;
                bf[nt][0] = Bs[(nb + r) * 32 + cl];
                bf[nt][1] = Bs[(nb + r) * 32 + ch];
            }
            #pragma unroll
            for (int mt = 0; mt < 2; mt++)
                #pragma unroll
                for (int nt = 0; nt < 8; nt++)
                    mma_tf32(acc[mt][nt], af[mt], bf[nt]);
        }
    }

    if (MODE == 1) {
        int n0 = blockIdx.x * BN;
        int c2 = (lane & 3) * 2;
        #pragma unroll
        for (int mt = 0; mt < 2; mt++) {
            #pragma unroll
            for (int half = 0; half < 2; half++) {
                int row = m0 + warpM * 32 + mt * 16 + half * 8 + r;
                if (row >= cnt) continue;
                float sc = rowScale ? rowScale[row] : 1.f;
                float* crow = C + (long)row * I + n0 + warpN * 64;
                #pragma unroll
                for (int nt = 0; nt < 8; nt++) {
                    float2 v;
                    v.x = acc[mt][nt][half * 2 + 0] * sc;
                    v.y = acc[mt][nt][half * 2 + 1] * sc;
                    *(float2*)(crow + nt * 8 + c2) = v;
                }
            }
        }
    } else {
        // stage accumulators through smem to pair gate/up columns (cp.async fully drained)
        __syncthreads();
        float* Cs = smem;               // [128][132]
        int c2 = (lane & 3) * 2;
        #pragma unroll
        for (int mt = 0; mt < 2; mt++)
            #pragma unroll
            for (int half = 0; half < 2; half++) {
                int rr = warpM * 32 + mt * 16 + half * 8 + r;
                #pragma unroll
                for (int nt = 0; nt < 8; nt++) {
                    float2 v;
                    v.x = acc[mt][nt][half * 2 + 0];
                    v.y = acc[mt][nt][half * 2 + 1];
                    *(float2*)(Cs + rr * 132 + warpN * 64 + nt * 8 + c2) = v;
                }
            }
        __syncthreads();
        int row = tid >> 1;
        int cb = (tid & 1) * 32;
        if (m0 + row < cnt) {
            float* crow = C + (long)(m0 + row) * I + n0g;
            #pragma unroll
            for (int j = 0; j < 32; j += 4) {
                float4 g = *(const float4*)(Cs + row * 132 + cb + j);
                float4 u = *(const float4*)(Cs + row * 132 + 64 + cb + j);
                uint4 o;
                o.x = to_tf32(g.x / (1.f + __expf(-g.x)) * u.x);
                o.y = to_tf32(g.y / (1.f + __expf(-g.y)) * u.y);
                o.z = to_tf32(g.z / (1.f + __expf(-g.z)) * u.z);
                o.w = to_tf32(g.w / (1.f + __expf(-g.w)) * u.w);
                *(uint4*)(crow + cb + j) = o;
            }
        }
    }
}

// ---------------- launch ----------------
static inline void round_launch(const float* in, float* out, long n) {
    long n4 = n >> 2;
    round_kernel<<<(unsigned)((n4 + 255) / 256), 256>>>(in, out, n4);
}

extern "C" void kernel_launch(void* const* d_in, const int* in_sizes, int n_in,
                              void* d_out, int out_size)
{
    (void)in_sizes; (void)n_in; (void)out_size;
    const float* x    = (const float*)d_in[0];
    const float* gw   = (const float*)d_in[1];
    const float* sgw  = (const float*)d_in[2];
    const float* sguw = (const float*)d_in[3];
    const float* sdw  = (const float*)d_in[4];
    const float* w13  = (const float*)d_in[5];
    const float* w2   = (const float*)d_in[6];
    float* out = (float*)d_out;

    float *xr, *sguwr, *sdwr, *w13r, *w2r, *actS, *eact, *moe, *gateS;
    int *counts, *perm;
    cudaGetSymbolAddress((void**)&xr,     g_xr);
    cudaGetSymbolAddress((void**)&sguwr,  g_sguwr);
    cudaGetSymbolAddress((void**)&sdwr,   g_sdwr);
    cudaGetSymbolAddress((void**)&w13r,   g_w13r);
    cudaGetSymbolAddress((void**)&w2r,    g_w2r);
    cudaGetSymbolAddress((void**)&actS,   g_actS);
    cudaGetSymbolAddress((void**)&eact,   g_eact);
    cudaGetSymbolAddress((void**)&moe,    g_moe);
    cudaGetSymbolAddress((void**)&gateS,  g_gateS);
    cudaGetSymbolAddress((void**)&counts, g_counts);
    cudaGetSymbolAddress((void**)&perm,   g_perm);

    cudaFuncSetAttribute(mma_gemm<0>, cudaFuncAttributeMaxDynamicSharedMemorySize, SMEM_TOTAL);
    cudaFuncSetAttribute(mma_gemm<1>, cudaFuncAttributeMaxDynamicSharedMemorySize, SMEM_TOTAL);

    init_kernel<<<1, 32>>>();
    router_kernel<<<MTOK, 256>>>(x, gw, sgw);

    // pre-round operands to tf32 (rna) once
    round_launch(x,    xr,    (long)MTOK * HDIM);
    round_launch(sguw, sguwr, (long)(2 * SHI) * HDIM);
    round_launch(sdw,  sdwr,  (long)HDIM * SHI);
    round_launch(w13,  w13r,  (long)NEXP * (2 * MOEI) * HDIM);
    round_launch(w2,   w2r,   (long)NEXP * HDIM * MOEI);

    // shared expert gate_up (fused silu*mul, tf32-rounded output)
    mma_gemm<0><<<dim3(SHI / 64, MTOK / BM, 1), 256, SMEM_TOTAL>>>(
        xr, sguwr, actS, SHI, HDIM, 0, 0, 0, nullptr, MTOK, nullptr, nullptr);
    // routed experts gate_up (gathered, fused silu*mul)
    mma_gemm<0><<<dim3(MOEI / 64, CAP / BM, NEXP), 256, SMEM_TOTAL>>>(
        xr, w13r, eact, MOEI, HDIM,
        0, (long)(2 * MOEI) * HDIM, (long)CAP * MOEI,
        counts, CAP, perm, nullptr);
    // shared down (fused sigmoid token gate) -> out
    mma_gemm<1><<<dim3(HDIM / BN, MTOK / BM, 1), 256, SMEM_TOTAL>>>(
        actS, sdwr, out, HDIM, SHI, 0, 0, 0, nullptr, MTOK, nullptr, gateS);
    // expert down
    mma_gemm<1><<<dim3(HDIM / BN, CAP / BM, NEXP), 256, SMEM_TOTAL>>>(
        eact, w2r, moe, HDIM, MOEI,
        (long)CAP * MOEI, (long)HDIM * MOEI, (long)CAP * HDIM,
        counts, CAP, nullptr, nullptr);

    combine_kernel<<<dim3((HDIM / 4 + 255) / 256, MTOK, 1), 256>>>(out);
}